// round 14
// baseline (speedup 1.0000x reference)
#include <cuda_runtime.h>
#include <cuda_fp16.h>
#include <math.h>
#include <float.h>
#include <cstdint>

#define TOKENS 16384
#define HIDDEN 4096
#define NEXP   256
#define TOPKG  4
#define TOPK   8

#define MT      128                // tokens per CTA
#define NTHREADS 512
#define KC      32
#define NCHUNK  (HIDDEN / KC)      // 128
#define RSTRIDE 80                 // 64B data + 16B pad -> conflict-free ldsm
#define AT      (MT * RSTRIDE)     // 10240 per A split tile
#define BT      (NEXP * RSTRIDE)   // 20480 per B split tile
#define BOFF    (2 * AT)           // 20480
#define STAGE_B (2 * AT + 2 * BT)  // 61440
#define NSTAGE  3
#define GPITCH  264
#define SMEM_TOTAL (NSTAGE * STAGE_B)   // 184320 (>= gates 135168)

#define WSCALE   1024.0f
#define WUNSCALE 0.0009765625f

// named split barriers: ids 1..3 = stage written (W), 4..6 = stage readers done (R)
#define BAR_SYNC(id)   asm volatile("bar.sync %0, 1024;"   :: "r"(id) : "memory")
#define BAR_ARRIVE(id) asm volatile("bar.arrive %0, 1024;" :: "r"(id) : "memory")

__device__ __forceinline__ uint32_t smem_u32(const void* p) {
    uint32_t a;
    asm("{ .reg .u64 t; cvta.to.shared.u64 t, %1; cvt.u32.u64 %0, t; }" : "=r"(a) : "l"(p));
    return a;
}
__device__ __forceinline__ void ldsm4(uint32_t* r, uint32_t addr) {
    asm volatile("ldmatrix.sync.aligned.m8n8.x4.shared.b16 {%0,%1,%2,%3}, [%4];"
                 : "=r"(r[0]), "=r"(r[1]), "=r"(r[2]), "=r"(r[3]) : "r"(addr));
}
__device__ __forceinline__ void mma16816(float* d, const uint32_t* a, uint32_t b0, uint32_t b1) {
    asm volatile(
        "mma.sync.aligned.m16n8k16.row.col.f32.f16.f16.f32 "
        "{%0,%1,%2,%3}, {%4,%5,%6,%7}, {%8,%9}, {%0,%1,%2,%3};"
        : "+f"(d[0]), "+f"(d[1]), "+f"(d[2]), "+f"(d[3])
        : "r"(a[0]), "r"(a[1]), "r"(a[2]), "r"(a[3]), "r"(b0), "r"(b1));
}

// split one float4 into 2 fp16x4 (hi + residual) and store 8B to each tile
__device__ __forceinline__ void split_store2(char* t0, char* t1, uint32_t off,
                                             float4 v, float scale) {
    float f[4] = {v.x, v.y, v.z, v.w};
    __align__(8) __half h0[4], h1[4];
#pragma unroll
    for (int j = 0; j < 4; j++) {
        float a = f[j] * scale;
        __half b0 = __float2half_rn(a);
        float r1 = a - __half2float(b0);
        h0[j] = b0; h1[j] = __float2half_rn(r1);
    }
    *(uint2*)(t0 + off) = *(uint2*)h0;
    *(uint2*)(t1 + off) = *(uint2*)h1;
}

// ---------------------------------------------------------------------------
// Fused MoE gate: GEMM (128 tokens x 256 experts per CTA, fp16 2-term split,
// 3 HMMA passes) + routing. Split-barrier pipeline with a 3-stage smem ring:
// stores of chunk k+2 posted at iter k, consumed at iter k+2 (2-chunk slack).
// ---------------------------------------------------------------------------
__global__ __launch_bounds__(NTHREADS, 1) void moe_gate_fused_kernel(
    const float* __restrict__ x, const float* __restrict__ w,
    const float* __restrict__ bias, float* __restrict__ out)
{
    extern __shared__ char smem[];
    const uint32_t smem_base = smem_u32(smem);
    const int tid  = threadIdx.x;
    const int lane = tid & 31;
    const int wid  = tid >> 5;
    const int m0 = blockIdx.x * MT;

    const int wm = (wid & 3) * 32;   // warp m offset (4-way over 128)
    const int wn = (wid >> 2) * 64;  // warp n offset (4-way over 256)

    const uint32_t a_lane = (uint32_t)((lane & 15) * RSTRIDE + (lane >> 4) * 16);
    const uint32_t b_lane = (uint32_t)(((lane & 7) + ((lane >> 4) & 1) * 8) * RSTRIDE +
                                       ((lane >> 3) & 1) * 16);

    // gmem mapping: idx = tid + 512*i ; row = idx>>3, c4 = idx&7
    const int r0 = tid >> 3;          // 0..63
    const int c4 = tid & 7;
    const float* xp = x + (size_t)(m0 + r0) * HIDDEN + c4 * 4;
    const float* wp = w + (size_t)r0 * HIDDEN + c4 * 4;
    const uint32_t sts_off = (uint32_t)(r0 * RSTRIDE + c4 * 8);

    float acc[2][8][4];
#pragma unroll
    for (int i = 0; i < 2; i++)
#pragma unroll
        for (int j = 0; j < 8; j++)
#pragma unroll
            for (int q = 0; q < 4; q++) acc[i][j][q] = 0.0f;

    float4 pa[2], pb[4];

    // ---- prologue: chunks 0,1 -> stages 0,1 ----
#pragma unroll
    for (int c = 0; c < 2; c++) {
        const float* xk = xp + c * KC;
        const float* wk = wp + c * KC;
#pragma unroll
        for (int i = 0; i < 2; i++) pa[i] = *(const float4*)(xk + (size_t)i * 64 * HIDDEN);
#pragma unroll
        for (int i = 0; i < 4; i++) pb[i] = *(const float4*)(wk + (size_t)i * 64 * HIDDEN);
        char* ab = smem + c * STAGE_B;
        char* bb = ab + BOFF;
#pragma unroll
        for (int i = 0; i < 2; i++)
            split_store2(ab, ab + AT, sts_off + i * 64 * RSTRIDE, pa[i], 1.0f);
#pragma unroll
        for (int i = 0; i < 4; i++)
            split_store2(bb, bb + BT, sts_off + i * 64 * RSTRIDE, pb[i], WSCALE);
    }
    // prime: stages 0,1 written; stage 2 free
    BAR_ARRIVE(1);
    BAR_ARRIVE(2);
    BAR_ARRIVE(6);

    // ---- main loop: 3-stage ring, split barriers ----
#pragma unroll 1
    for (int k = 0; k < NCHUNK; k++) {
        const int kn2 = k + 2;
        const int p = k % NSTAGE;          // stage of chunk k
        const int q = kn2 % NSTAGE;        // stage of chunk k+2

        // 1) prefetch chunk k+2 into regs (no barrier: registers only)
        if (kn2 < NCHUNK) {
            const float* xk = xp + kn2 * KC;
            const float* wk = wp + kn2 * KC;
#pragma unroll
            for (int i = 0; i < 2; i++) pa[i] = *(const float4*)(xk + (size_t)i * 64 * HIDDEN);
#pragma unroll
            for (int i = 0; i < 4; i++) pb[i] = *(const float4*)(wk + (size_t)i * 64 * HIDDEN);
        }

        // 2) wait stage p written, MMA, signal readers done
        BAR_SYNC(1 + p);

        const uint32_t stage = smem_base + (uint32_t)p * STAGE_B;
#pragma unroll
        for (int ks = 0; ks < 2; ks++) {
            const uint32_t ko = (uint32_t)(ks * 32);
            uint32_t fa[2][2][4];
#pragma unroll
            for (int s = 0; s < 2; s++) {
                const uint32_t abase = stage + s * AT + ko + a_lane;
                ldsm4(fa[s][0], abase + (uint32_t)(wm * RSTRIDE));
                ldsm4(fa[s][1], abase + (uint32_t)((wm + 16) * RSTRIDE));
            }
            uint32_t fb[2][4][4];
#pragma unroll
            for (int s = 0; s < 2; s++) {
                const uint32_t bbase = stage + BOFF + s * BT + ko + b_lane;
#pragma unroll
                for (int jn = 0; jn < 4; jn++)
                    ldsm4(fb[s][jn], bbase + (uint32_t)((wn + jn * 16) * RSTRIDE));
            }
            // passes: a0*b0, a0*b1, a1*b0
#pragma unroll
            for (int mt = 0; mt < 2; mt++)
#pragma unroll
                for (int j = 0; j < 8; j++)
                    mma16816(acc[mt][j], fa[0][mt],
                             fb[0][j >> 1][(j & 1) * 2], fb[0][j >> 1][(j & 1) * 2 + 1]);
#pragma unroll
            for (int mt = 0; mt < 2; mt++)
#pragma unroll
                for (int j = 0; j < 8; j++)
                    mma16816(acc[mt][j], fa[0][mt],
                             fb[1][j >> 1][(j & 1) * 2], fb[1][j >> 1][(j & 1) * 2 + 1]);
#pragma unroll
            for (int mt = 0; mt < 2; mt++)
#pragma unroll
                for (int j = 0; j < 8; j++)
                    mma16816(acc[mt][j], fa[1][mt],
                             fb[0][j >> 1][(j & 1) * 2], fb[0][j >> 1][(j & 1) * 2 + 1]);
        }

        BAR_ARRIVE(4 + p);     // done reading stage p (non-blocking)

        // 3) wait stage q free, store chunk k+2, signal written
        if (kn2 < NCHUNK) {
            BAR_SYNC(4 + q);   // readers of stage q (chunk k-1) all done
            char* base = smem + q * STAGE_B;
            char* ab = base;        char* bb = base + BOFF;
#pragma unroll
            for (int i = 0; i < 2; i++)
                split_store2(ab, ab + AT, sts_off + i * 64 * RSTRIDE, pa[i], 1.0f);
#pragma unroll
            for (int i = 0; i < 4; i++)
                split_store2(bb, bb + BT, sts_off + i * 64 * RSTRIDE, pb[i], WSCALE);
            BAR_ARRIVE(1 + q); // stage q written (non-blocking)
        }
    }

    __syncthreads();  // all MMA done before gates overlay reuses smem

    // ---- write gates to smem (undo the 2^10 w pre-scale) ----
    float* gsm = (float*)smem;
    {
        const int g = lane >> 2;
        const int tq = lane & 3;
#pragma unroll
        for (int mt = 0; mt < 2; mt++) {
#pragma unroll
            for (int j = 0; j < 8; j++) {
                int row = wm + mt * 16 + g;
                int col = wn + j * 8 + tq * 2;
                float2* p0 = (float2*)&gsm[row * GPITCH + col];
                float2* p1 = (float2*)&gsm[(row + 8) * GPITCH + col];
                *p0 = make_float2(acc[mt][j][0] * WUNSCALE, acc[mt][j][1] * WUNSCALE);
                *p1 = make_float2(acc[mt][j][2] * WUNSCALE, acc[mt][j][3] * WUNSCALE);
            }
        }
    }
    __syncthreads();

    // ---- routing: warp wid handles tokens wid*8 .. wid*8+7 (16*8 = 128) ----
    const unsigned FULL = 0xFFFFFFFFu;
#pragma unroll 1
    for (int tl = wid * 8; tl < wid * 8 + 8; tl++) {
        const int t = m0 + tl;
        float orig[8], v[8];
        float m1 = -FLT_MAX, m2 = -FLT_MAX;
#pragma unroll
        for (int j = 0; j < 8; j++) {
            int e = lane * 8 + j;
            float gv = gsm[tl * GPITCH + e];
            float s;
            if (gv >= 0.0f) { s = 1.0f / (1.0f + expf(-gv)); }
            else { float eg = expf(gv); s = eg / (1.0f + eg); }
            orig[j] = s;
            float sc2 = s + __ldg(&bias[e]);
            v[j] = sc2;
            if (sc2 > m1) { m2 = m1; m1 = sc2; }
            else if (sc2 > m2) { m2 = sc2; }
        }

#pragma unroll
        for (int off = 1; off <= 2; off <<= 1) {
            float o1 = __shfl_xor_sync(FULL, m1, off);
            float o2 = __shfl_xor_sync(FULL, m2, off);
            if (o1 > m1) { m2 = fmaxf(m1, o2); m1 = o1; }
            else         { m2 = fmaxf(m2, o1); }
        }
        float gs = m1 + m2;

        float gsg = __shfl_sync(FULL, gs, (lane & 7) * 4);

        int gidx = lane & 7;
        int rank = 0;
#pragma unroll
        for (int h = 0; h < 8; h++) {
            float other = __shfl_sync(FULL, gsg, h);
            rank += (other < gsg || (other == gsg && h < gidx)) ? 1 : 0;
        }
        unsigned keepmask = __ballot_sync(FULL, (lane < 8) && (rank < TOPKG));
        bool kept = (keepmask >> (lane >> 2)) & 1u;

#pragma unroll
        for (int j = 0; j < 8; j++) v[j] = kept ? v[j] : 0.0f;

        int selIdx[8]; float selOrig[8]; float ssum = 0.0f;
#pragma unroll
        for (int k = 0; k < TOPK; k++) {
            float bv = FLT_MAX; int bi = 0x7FFFFFFF; float bo = 0.0f;
#pragma unroll
            for (int j = 0; j < 8; j++) {
                int e = lane * 8 + j;
                if (v[j] < bv || (v[j] == bv && e < bi)) { bv = v[j]; bi = e; bo = orig[j]; }
            }
#pragma unroll
            for (int off = 16; off > 0; off >>= 1) {
                float ov = __shfl_xor_sync(FULL, bv, off);
                int   oi = __shfl_xor_sync(FULL, bi, off);
                float oo = __shfl_xor_sync(FULL, bo, off);
                if (ov < bv || (ov == bv && oi < bi)) { bv = ov; bi = oi; bo = oo; }
            }
            selIdx[k] = bi; selOrig[k] = bo; ssum += bo;
            if ((bi >> 3) == lane) v[bi & 7] = FLT_MAX;
        }

        float inv = 2.5f / (ssum + 1e-20f);
        if (lane < 8) {
            out[(size_t)t * TOPK + lane] = (float)selIdx[lane];
            out[(size_t)TOKENS * TOPK + (size_t)t * TOPK + lane] = selOrig[lane] * inv;
        }
    }
}

extern "C" void kernel_launch(void* const* d_in, const int* in_sizes, int n_in,
                              void* d_out, int out_size)
{
    const float* x    = (const float*)d_in[0];
    const float* w    = (const float*)d_in[1];
    const float* bias = (const float*)d_in[2];
    float* out = (float*)d_out;

    cudaFuncSetAttribute(moe_gate_fused_kernel,
                         cudaFuncAttributeMaxDynamicSharedMemorySize, SMEM_TOTAL);
    moe_gate_fused_kernel<<<TOKENS / MT, NTHREADS, SMEM_TOTAL>>>(x, w, bias, out);
}